// round 15
// baseline (speedup 1.0000x reference)
#include <cuda_runtime.h>
#include <cuda_fp16.h>
#include <cstdint>
#include <cstring>

// SpatialAttention2D: B=4, H=W=48, C=64, NH=4, KD=64, S=2304
#define S_TOT 2304
#define BATCH 4
#define ROWS_TOT (BATCH * S_TOT)            // 9216
#define QKV_STRIDE ((size_t)ROWS_TOT * 256) // per-projection element count

__device__ __half g_qkv[3 * ROWS_TOT * 256]; // fp16, RN-rounded, q pre-scaled
__device__ __half g_ctx[ROWS_TOT * 256];     // fp16 attention output
__device__ __half g_wo16[256 * 64];          // Wo fp16 (converted by qkv y==3)

__device__ __forceinline__ uint32_t h2_as_u32(__half2 h) {
    uint32_t u;
    memcpy(&u, &h, 4);
    return u;
}

__device__ __forceinline__ void mma_f16(float& c0, float& c1, float& c2, float& c3,
                                        uint32_t a0, uint32_t a1, uint32_t a2, uint32_t a3,
                                        uint32_t b0, uint32_t b1) {
    asm volatile(
        "mma.sync.aligned.m16n8k16.row.col.f32.f16.f16.f32 "
        "{%0,%1,%2,%3}, {%4,%5,%6,%7}, {%8,%9}, {%0,%1,%2,%3};"
        : "+f"(c0), "+f"(c1), "+f"(c2), "+f"(c3)
        : "r"(a0), "r"(a1), "r"(a2), "r"(a3), "r"(b0), "r"(b1));
}

__device__ __forceinline__ void ldm_x4(uint32_t& r0, uint32_t& r1,
                                       uint32_t& r2, uint32_t& r3, uint32_t addr) {
    asm volatile("ldmatrix.sync.aligned.m8n8.x4.shared.b16 {%0,%1,%2,%3}, [%4];"
                 : "=r"(r0), "=r"(r1), "=r"(r2), "=r"(r3) : "r"(addr));
}
__device__ __forceinline__ void ldm_x4_t(uint32_t& r0, uint32_t& r1,
                                         uint32_t& r2, uint32_t& r3, uint32_t addr) {
    asm volatile("ldmatrix.sync.aligned.m8n8.x4.trans.shared.b16 {%0,%1,%2,%3}, [%4];"
                 : "=r"(r0), "=r"(r1), "=r"(r2), "=r"(r3) : "r"(addr));
}

__device__ __forceinline__ void cp_async16(uint32_t saddr, const void* gptr) {
    asm volatile("cp.async.cg.shared.global [%0], [%1], 16;" ::
                 "r"(saddr), "l"(gptr));
}
__device__ __forceinline__ void cp_commit() {
    asm volatile("cp.async.commit_group;");
}
__device__ __forceinline__ void cp_wait1() {
    asm volatile("cp.async.wait_group 1;");
}
#define CP_WAIT_N(n) asm volatile("cp.async.wait_group %0;" :: "n"(n))

#define XWH 72
#define WSH 264   // qkv Ws stride (256 + 8) halves; odd multiple of 8 -> conflict-free
#define ONES_H2 0x3C003C00u   // half2(1.0, 1.0)

// ---------------------------------------------------------------------------
// Kernel A: fused pos-add + QKV projection on fp16 tensor cores.
// grid (144, 4): y<3 = projection; y==3 converts Wo -> fp16 (16 blocks).
// q pre-scaled by (1/sqrt(64)) * log2(e).
// ---------------------------------------------------------------------------
__global__ __launch_bounds__(256) void qkv_proj_kernel(
    const float* __restrict__ inp, const float* __restrict__ outp,
    const float* __restrict__ pos_y, const float* __restrict__ pos_x,
    const float* __restrict__ Wq, const float* __restrict__ bq,
    const float* __restrict__ Wk, const float* __restrict__ bk,
    const float* __restrict__ Wv, const float* __restrict__ bv,
    const float* __restrict__ Wo)
{
    const int proj = blockIdx.y;
    const int tid = threadIdx.x;

    if (proj == 3) {   // Wo fp32 -> fp16 conversion
        if (blockIdx.x < 16) {
            int idx = blockIdx.x * 256 + tid;   // 0..4095
            float4 w = *(const float4*)&Wo[idx * 4];
            __half2* d = (__half2*)&g_wo16[idx * 4];
            d[0] = __floats2half2_rn(w.x, w.y);
            d[1] = __floats2half2_rn(w.z, w.w);
        }
        return;
    }

    __shared__ __align__(16) __half Xs[64 * XWH];   // 9216 B
    __shared__ __align__(16) __half Ws[64 * WSH];   // 33792 B

    const int wid  = tid >> 5;
    const int lane = tid & 31;
    const int gid  = lane >> 2;
    const int tig  = lane & 3;
    const int grp  = lane >> 3;
    const int l8   = lane & 7;
    const int wm0  = (wid & 3) * 16;   // row group
    const int jt0  = (wid >> 2) * 128; // col group

    const int m0 = blockIdx.x * 64;
    const int b = m0 / S_TOT;
    const int s0 = m0 % S_TOT;

    const float* src  = (proj == 0) ? outp : inp;
    const float* W    = (proj == 0) ? Wq : (proj == 1) ? Wk : Wv;
    const float* bias = (proj == 0) ? bq : (proj == 1) ? bk : bv;

    // X tile: 64 rows x 64 c, pos added, fp16
#pragma unroll
    for (int p = 0; p < 4; p++) {
        int idx = tid + p * 256;
        int r = idx >> 4;
        int c4 = (idx & 15) * 4;
        int srow = s0 + r;
        int y = srow / 48, x = srow % 48;
        float4 a  = *(const float4*)&src[((size_t)(b * S_TOT + srow)) * 64 + c4];
        float4 py = *(const float4*)&pos_y[y * 64 + c4];
        float4 px = *(const float4*)&pos_x[x * 64 + c4];
        __half2* d = (__half2*)&Xs[r * XWH + c4];
        d[0] = __floats2half2_rn(a.x + py.x + px.x, a.y + py.y + px.y);
        d[1] = __floats2half2_rn(a.z + py.z + px.z, a.w + py.w + px.w);
    }
    // W tile: 64 c-rows x 256 cols, fp16
#pragma unroll
    for (int p = 0; p < 16; p++) {
        int idx = tid + p * 256;
        int c = idx >> 6;
        int j4 = (idx & 63) * 4;
        float4 w = *(const float4*)&W[c * 256 + j4];
        __half2* d = (__half2*)&Ws[c * WSH + j4];
        d[0] = __floats2half2_rn(w.x, w.y);
        d[1] = __floats2half2_rn(w.z, w.w);
    }
    __syncthreads();

    const uint32_t xs_u32 = (uint32_t)__cvta_generic_to_shared(Xs);
    const uint32_t ws_u32 = (uint32_t)__cvta_generic_to_shared(Ws);

    uint32_t qa[4][4];
#pragma unroll
    for (int k = 0; k < 4; k++) {
        uint32_t addr = xs_u32 +
            ((wm0 + (grp & 1) * 8 + l8) * XWH + k * 16 + (grp >> 1) * 8) * 2;
        ldm_x4(qa[k][0], qa[k][1], qa[k][2], qa[k][3], addr);
    }

    float acc[16][4];
#pragma unroll
    for (int n = 0; n < 16; n++)
        acc[n][0] = acc[n][1] = acc[n][2] = acc[n][3] = 0.f;

    const int w_row_off = (grp & 1) * 8 + l8;
    const int w_col_off = (grp >> 1) * 8;
#pragma unroll
    for (int k = 0; k < 4; k++) {
#pragma unroll
        for (int nt = 0; nt < 8; nt++) {
            uint32_t b0, b1, b2, b3;
            uint32_t addr = ws_u32 +
                ((k * 16 + w_row_off) * WSH + jt0 + nt * 16 + w_col_off) * 2;
            ldm_x4_t(b0, b1, b2, b3, addr);
            mma_f16(acc[2*nt][0], acc[2*nt][1], acc[2*nt][2], acc[2*nt][3],
                    qa[k][0], qa[k][1], qa[k][2], qa[k][3], b0, b1);
            mma_f16(acc[2*nt+1][0], acc[2*nt+1][1], acc[2*nt+1][2], acc[2*nt+1][3],
                    qa[k][0], qa[k][1], qa[k][2], qa[k][3], b2, b3);
        }
    }

    const float sc = (proj == 0) ? 0.125f * 1.4426950408889634f : 1.0f;
    __half* dst = g_qkv + (size_t)proj * QKV_STRIDE;
    const size_t row0 = (size_t)(m0 + wm0 + gid) * 256 + jt0;
    const size_t row1 = (size_t)(m0 + wm0 + gid + 8) * 256 + jt0;
#pragma unroll
    for (int n = 0; n < 16; n++) {
        float2 bb = *(const float2*)&bias[jt0 + n * 8 + 2 * tig];
        *(__half2*)&dst[row0 + n * 8 + 2 * tig] =
            __floats2half2_rn((acc[n][0] + bb.x) * sc, (acc[n][1] + bb.y) * sc);
        *(__half2*)&dst[row1 + n * 8 + 2 * tig] =
            __floats2half2_rn((acc[n][2] + bb.x) * sc, (acc[n][3] + bb.y) * sc);
    }
}

// ---------------------------------------------------------------------------
// Kernel B: flash attention, fp16 m16n8k16 mma, 3-stage cp.async pipeline
// (refill after compute; one sync/iter). Softmax: p = ex2.approx.f16x2 of
// pairwise-converted scores (halves MUFU work); l accumulated by an extra
// all-ones-B mma per j (no smem, no FADD chain, normalization uses the
// exact fp16 p's that GEMM2 consumes).
// Dynamic smem: Ks0..2 | Vs0..2, each 64*72 halves -> 55296 B.
// ---------------------------------------------------------------------------
#define KVH 72
#define NUM_KT 36
#define STG_BYTES (64 * KVH * 2)            // 9216
#define ATTN_DYN_BYTES (6 * STG_BYTES)      // 55296

__global__ __launch_bounds__(256, 2) void attn_kernel()
{
    extern __shared__ __align__(16) __half dyn_sm[];

    const int tid  = threadIdx.x;
    const int wid  = tid >> 5;
    const int lane = tid & 31;
    const int gid  = lane >> 2;
    const int tig  = lane & 3;
    const int grp  = lane >> 3;
    const int l8   = lane & 7;
    const int wm0  = wid * 16;

    const int m0 = blockIdx.x * 128;
    const int bh = blockIdx.y;
    const int b = bh >> 2, h = bh & 3;

    const __half* qbase = g_qkv + ((size_t)(b * S_TOT)) * 256 + h * 64;
    const __half* kbase = g_qkv + QKV_STRIDE     + ((size_t)(b * S_TOT)) * 256 + h * 64;
    const __half* vbase = g_qkv + 2 * QKV_STRIDE + ((size_t)(b * S_TOT)) * 256 + h * 64;

    const uint32_t base_u32 = (uint32_t)__cvta_generic_to_shared(dyn_sm);
    const uint32_t ksb[3] = { base_u32, base_u32 + STG_BYTES, base_u32 + 2 * STG_BYTES };
    const uint32_t vsb[3] = { base_u32 + 3 * STG_BYTES, base_u32 + 4 * STG_BYTES,
                              base_u32 + 5 * STG_BYTES };

    auto issue_tile = [&](int kt, int stg) {
#pragma unroll
        for (int p = 0; p < 2; p++) {
            int idx = tid + p * 256;
            int tok = idx >> 3;
            int hc  = (idx & 7) * 8;
            size_t grow = (size_t)(kt * 64 + tok) * 256 + hc;
            cp_async16(ksb[stg] + (tok * KVH + hc) * 2, kbase + grow);
            cp_async16(vsb[stg] + (tok * KVH + hc) * 2, vbase + grow);
        }
    };

    issue_tile(0, 0); cp_commit();
    issue_tile(1, 1); cp_commit();

    // Q fragments direct from gmem (L2-resident)
    uint32_t qa[4][4];
    {
        const __half* qr0 = qbase + (size_t)(m0 + wm0 + gid) * 256;
        const __half* qr1 = qr0 + (size_t)8 * 256;
#pragma unroll
        for (int k = 0; k < 4; k++) {
            qa[k][0] = *(const uint32_t*)&qr0[k * 16 + 2 * tig];
            qa[k][1] = *(const uint32_t*)&qr1[k * 16 + 2 * tig];
            qa[k][2] = *(const uint32_t*)&qr0[k * 16 + 2 * tig + 8];
            qa[k][3] = *(const uint32_t*)&qr1[k * 16 + 2 * tig + 8];
        }
    }

    const int k_tok_off = (grp >> 1) * 8 + l8;
    const int k_col_off = (grp & 1) * 8;
    const int v_tok_off = (grp & 1) * 8 + l8;
    const int v_d_off   = (grp >> 1) * 8;

    float oacc[8][4];
#pragma unroll
    for (int n = 0; n < 8; n++)
        oacc[n][0] = oacc[n][1] = oacc[n][2] = oacc[n][3] = 0.f;
    float lacc[4] = {0.f, 0.f, 0.f, 0.f};   // all-ones-column accumulator

    int buf = 0;
    for (int kt = 0; kt < NUM_KT; kt++) {
        cp_wait1();
        __syncthreads();

        // ---- GEMM1: S = Q * K^T ----
        float sacc[8][4];
#pragma unroll
        for (int n = 0; n < 8; n++)
            sacc[n][0] = sacc[n][1] = sacc[n][2] = sacc[n][3] = 0.f;
#pragma unroll
        for (int k = 0; k < 4; k++) {
#pragma unroll
            for (int ntp = 0; ntp < 4; ntp++) {
                uint32_t b0, b1, b2, b3;
                uint32_t addr = ksb[buf] +
                    ((ntp * 16 + k_tok_off) * KVH + k * 16 + k_col_off) * 2;
                ldm_x4(b0, b1, b2, b3, addr);
                mma_f16(sacc[2*ntp][0], sacc[2*ntp][1], sacc[2*ntp][2], sacc[2*ntp][3],
                        qa[k][0], qa[k][1], qa[k][2], qa[k][3], b0, b1);
                mma_f16(sacc[2*ntp+1][0], sacc[2*ntp+1][1], sacc[2*ntp+1][2], sacc[2*ntp+1][3],
                        qa[k][0], qa[k][1], qa[k][2], qa[k][3], b2, b3);
            }
        }

        // ---- Softmax numerator: p = ex2.approx.f16x2 (paired) ----
        uint32_t ph[8][2];
#pragma unroll
        for (int n = 0; n < 8; n++) {
            __half2 s01 = __floats2half2_rn(sacc[n][0], sacc[n][1]);
            __half2 s23 = __floats2half2_rn(sacc[n][2], sacc[n][3]);
            ph[n][0] = h2_as_u32(h2exp2(s01));
            ph[n][1] = h2_as_u32(h2exp2(s23));
        }

        // ---- GEMM2: O += P * V; l += P * ones (constant B fragment) ----
#pragma unroll
        for (int j = 0; j < 4; j++) {
            uint32_t a0 = ph[2*j][0],   a1 = ph[2*j][1];
            uint32_t a2 = ph[2*j+1][0], a3 = ph[2*j+1][1];
#pragma unroll
            for (int ntp = 0; ntp < 4; ntp++) {
                uint32_t b0, b1, b2, b3;
                uint32_t addr = vsb[buf] +
                    ((j * 16 + v_tok_off) * KVH + ntp * 16 + v_d_off) * 2;
                ldm_x4_t(b0, b1, b2, b3, addr);
                mma_f16(oacc[2*ntp][0], oacc[2*ntp][1], oacc[2*ntp][2], oacc[2*ntp][3],
                        a0, a1, a2, a3, b0, b1);
                mma_f16(oacc[2*ntp+1][0], oacc[2*ntp+1][1], oacc[2*ntp+1][2], oacc[2*ntp+1][3],
                        a0, a1, a2, a3, b2, b3);
            }
            // l row-sums: B = all ones -> every C column holds sum_k p
            mma_f16(lacc[0], lacc[1], lacc[2], lacc[3],
                    a0, a1, a2, a3, ONES_H2, ONES_H2);
        }

        // Refill AFTER compute; target (buf+2)%3 = iter kt-1's buffer.
        if (kt + 2 < NUM_KT) {
            int nstg = buf + 2; if (nstg >= 3) nstg -= 3;
            issue_tile(kt + 2, nstg);
        }
        cp_commit();
        buf++; if (buf == 3) buf = 0;
    }

    // ---- Epilogue: normalize (l = lacc, no reduction needed), store fp16 ----
    float inv0 = 1.0f / lacc[0];   // row wm0+gid: full-row sum of p
    float inv1 = 1.0f / lacc[2];   // row wm0+gid+8
    __half* c0p = g_ctx + (size_t)(b * S_TOT + m0 + wm0 + gid) * 256 + h * 64;
    __half* c1p = g_ctx + (size_t)(b * S_TOT + m0 + wm0 + gid + 8) * 256 + h * 64;
#pragma unroll
    for (int n = 0; n < 8; n++) {
        *(__half2*)&c0p[n * 8 + 2 * tig] =
            __floats2half2_rn(oacc[n][0] * inv0, oacc[n][1] * inv0);
        *(__half2*)&c1p[n * 8 + 2 * tig] =
            __floats2half2_rn(oacc[n][2] * inv1, oacc[n][3] * inv1);
    }
}

// ---------------------------------------------------------------------------
// Kernel C: output projection on fp16 tensor cores.
// grid 144, 128 thr = 4 warps; Wo staged via 4 chunked cp.async groups
// with progressive waits (compute chunk c overlaps flight of c+1..3).
// ---------------------------------------------------------------------------
__global__ __launch_bounds__(128) void out_proj_kernel(
    const float* __restrict__ bo, float* __restrict__ out)
{
    __shared__ __align__(16) __half Wos[256 * XWH];

    const int tid  = threadIdx.x;
    const int wid  = tid >> 5;
    const int lane = tid & 31;
    const int gid  = lane >> 2;
    const int tig  = lane & 3;
    const int grp  = lane >> 3;
    const int l8   = lane & 7;
    const int wm0  = wid * 16;
    const int m0 = blockIdx.x * 64;

    const uint32_t ws_u32 = (uint32_t)__cvta_generic_to_shared(Wos);

#pragma unroll
    for (int c = 0; c < 4; c++) {
#pragma unroll
        for (int p = 0; p < 4; p++) {
            int idx = tid + p * 128;            // 0..511
            int r  = c * 64 + (idx >> 3);
            int ch = (idx & 7) * 8;
            cp_async16(ws_u32 + (r * XWH + ch) * 2, g_wo16 + r * 64 + ch);
        }
        cp_commit();
    }

    const int w_row_off = (grp & 1) * 8 + l8;
    const int w_col_off = (grp >> 1) * 8;

    const __half* cr0 = g_ctx + (size_t)(m0 + wm0 + gid) * 256;
    const __half* cr1 = cr0 + (size_t)8 * 256;

    float acc[8][4];
#pragma unroll
    for (int n = 0; n < 8; n++)
        acc[n][0] = acc[n][1] = acc[n][2] = acc[n][3] = 0.f;

#define OUT_CHUNK(c)                                                          \
    do {                                                                      \
        CP_WAIT_N(3 - (c));                                                   \
        __syncthreads();                                                      \
        _Pragma("unroll")                                                     \
        for (int kk = 0; kk < 4; kk++) {                                      \
            int k = (c) * 4 + kk;                                             \
            uint32_t a0 = *(const uint32_t*)&cr0[k * 16 + 2 * tig];           \
            uint32_t a1 = *(const uint32_t*)&cr1[k * 16 + 2 * tig];           \
            uint32_t a2 = *(const uint32_t*)&cr0[k * 16 + 2 * tig + 8];       \
            uint32_t a3 = *(const uint32_t*)&cr1[k * 16 + 2 * tig + 8];       \
            _Pragma("unroll")                                                 \
            for (int nt = 0; nt < 4; nt++) {                                  \
                uint32_t b0, b1, b2, b3;                                      \
                uint32_t addr = ws_u32 +                                      \
                    ((k * 16 + w_row_off) * XWH + nt * 16 + w_col_off) * 2;   \
                ldm_x4_t(b0, b1, b2, b3, addr);                               \
                mma_f16(acc[2*nt][0], acc[2*nt][1], acc[2*nt][2], acc[2*nt][3],\
                        a0, a1, a2, a3, b0, b1);                              \
                mma_f16(acc[2*nt+1][0], acc[2*nt+1][1], acc[2*nt+1][2],       \
                        acc[2*nt+1][3], a0, a1, a2, a3, b2, b3);              \
            }                                                                 \
        }                                                                     \
    } while (0)

    OUT_CHUNK(0);
    OUT_CHUNK(1);
    OUT_CHUNK(2);
    OUT_CHUNK(3);
#undef OUT_CHUNK

    const size_t row0 = (size_t)(m0 + wm0 + gid) * 64;
    const size_t row1 = (size_t)(m0 + wm0 + gid + 8) * 64;
#pragma unroll
    for (int n = 0; n < 8; n++) {
        float2 bb = *(const float2*)&bo[n * 8 + 2 * tig];
        *(float2*)&out[row0 + n * 8 + 2 * tig] =
            make_float2(acc[n][0] + bb.x, acc[n][1] + bb.y);
        *(float2*)&out[row1 + n * 8 + 2 * tig] =
            make_float2(acc[n][2] + bb.x, acc[n][3] + bb.y);
    }
}

// ---------------------------------------------------------------------------
extern "C" void kernel_launch(void* const* d_in, const int* in_sizes, int n_in,
                              void* d_out, int out_size)
{
    const float* inp   = (const float*)d_in[0];
    const float* outp  = (const float*)d_in[1];
    const float* pos_y = (const float*)d_in[2];
    const float* pos_x = (const float*)d_in[3];
    const float* Wq    = (const float*)d_in[4];
    const float* bq    = (const float*)d_in[5];
    const float* Wk    = (const float*)d_in[6];
    const float* bk    = (const float*)d_in[7];
    const float* Wv    = (const float*)d_in[8];
    const float* bv    = (const float*)d_in[9];
    const float* Wo    = (const float*)d_in[10];
    const float* bo    = (const float*)d_in[11];

    (void)cudaFuncSetAttribute(attn_kernel,
                               cudaFuncAttributeMaxDynamicSharedMemorySize,
                               ATTN_DYN_BYTES);

    qkv_proj_kernel<<<dim3(144, 4), 256>>>(inp, outp, pos_y, pos_x,
                                           Wq, bq, Wk, bk, Wv, bv, Wo);
    attn_kernel<<<dim3(18, 16), 256, ATTN_DYN_BYTES>>>();
    out_proj_kernel<<<144, 128>>>(bo, (float*)d_out);
}

// round 16
// speedup vs baseline: 1.0563x; 1.0563x over previous
#include <cuda_runtime.h>
#include <cuda_fp16.h>
#include <cstdint>
#include <cstring>

// SpatialAttention2D: B=4, H=W=48, C=64, NH=4, KD=64, S=2304
#define S_TOT 2304
#define BATCH 4
#define ROWS_TOT (BATCH * S_TOT)            // 9216
#define QKV_STRIDE ((size_t)ROWS_TOT * 256) // per-projection element count

__device__ __half g_qkv[3 * ROWS_TOT * 256]; // fp16, RN-rounded, q pre-scaled
__device__ __half g_ctx[ROWS_TOT * 256];     // fp16 attention output
__device__ __half g_wo16[256 * 64];          // Wo fp16 (converted by qkv y==3)

__device__ __forceinline__ uint32_t h2_as_u32(__half2 h) {
    uint32_t u;
    memcpy(&u, &h, 4);
    return u;
}

__device__ __forceinline__ void mma_f16(float& c0, float& c1, float& c2, float& c3,
                                        uint32_t a0, uint32_t a1, uint32_t a2, uint32_t a3,
                                        uint32_t b0, uint32_t b1) {
    asm volatile(
        "mma.sync.aligned.m16n8k16.row.col.f32.f16.f16.f32 "
        "{%0,%1,%2,%3}, {%4,%5,%6,%7}, {%8,%9}, {%0,%1,%2,%3};"
        : "+f"(c0), "+f"(c1), "+f"(c2), "+f"(c3)
        : "r"(a0), "r"(a1), "r"(a2), "r"(a3), "r"(b0), "r"(b1));
}

__device__ __forceinline__ void ldm_x4(uint32_t& r0, uint32_t& r1,
                                       uint32_t& r2, uint32_t& r3, uint32_t addr) {
    asm volatile("ldmatrix.sync.aligned.m8n8.x4.shared.b16 {%0,%1,%2,%3}, [%4];"
                 : "=r"(r0), "=r"(r1), "=r"(r2), "=r"(r3) : "r"(addr));
}
__device__ __forceinline__ void ldm_x4_t(uint32_t& r0, uint32_t& r1,
                                         uint32_t& r2, uint32_t& r3, uint32_t addr) {
    asm volatile("ldmatrix.sync.aligned.m8n8.x4.trans.shared.b16 {%0,%1,%2,%3}, [%4];"
                 : "=r"(r0), "=r"(r1), "=r"(r2), "=r"(r3) : "r"(addr));
}

__device__ __forceinline__ void cp_async16(uint32_t saddr, const void* gptr) {
    asm volatile("cp.async.cg.shared.global [%0], [%1], 16;" ::
                 "r"(saddr), "l"(gptr));
}
__device__ __forceinline__ void cp_commit() {
    asm volatile("cp.async.commit_group;");
}
__device__ __forceinline__ void cp_wait1() {
    asm volatile("cp.async.wait_group 1;");
}
#define CP_WAIT_N(n) asm volatile("cp.async.wait_group %0;" :: "n"(n))

#define XWH 72
#define WSH 264   // qkv Ws stride (256 + 8) halves; odd multiple of 8 -> conflict-free

// ---------------------------------------------------------------------------
// Kernel A: fused pos-add + QKV projection on fp16 tensor cores.
// grid (144, 4): y<3 = projection; y==3 converts Wo -> fp16 (16 blocks).
// q pre-scaled by (1/sqrt(64)) * log2(e).  (round-14 exact)
// ---------------------------------------------------------------------------
__global__ __launch_bounds__(256) void qkv_proj_kernel(
    const float* __restrict__ inp, const float* __restrict__ outp,
    const float* __restrict__ pos_y, const float* __restrict__ pos_x,
    const float* __restrict__ Wq, const float* __restrict__ bq,
    const float* __restrict__ Wk, const float* __restrict__ bk,
    const float* __restrict__ Wv, const float* __restrict__ bv,
    const float* __restrict__ Wo)
{
    const int proj = blockIdx.y;
    const int tid = threadIdx.x;

    if (proj == 3) {   // Wo fp32 -> fp16 conversion
        if (blockIdx.x < 16) {
            int idx = blockIdx.x * 256 + tid;   // 0..4095
            float4 w = *(const float4*)&Wo[idx * 4];
            __half2* d = (__half2*)&g_wo16[idx * 4];
            d[0] = __floats2half2_rn(w.x, w.y);
            d[1] = __floats2half2_rn(w.z, w.w);
        }
        return;
    }

    __shared__ __align__(16) __half Xs[64 * XWH];   // 9216 B
    __shared__ __align__(16) __half Ws[64 * WSH];   // 33792 B

    const int wid  = tid >> 5;
    const int lane = tid & 31;
    const int gid  = lane >> 2;
    const int tig  = lane & 3;
    const int grp  = lane >> 3;
    const int l8   = lane & 7;
    const int wm0  = (wid & 3) * 16;   // row group
    const int jt0  = (wid >> 2) * 128; // col group

    const int m0 = blockIdx.x * 64;
    const int b = m0 / S_TOT;
    const int s0 = m0 % S_TOT;

    const float* src  = (proj == 0) ? outp : inp;
    const float* W    = (proj == 0) ? Wq : (proj == 1) ? Wk : Wv;
    const float* bias = (proj == 0) ? bq : (proj == 1) ? bk : bv;

    // X tile: 64 rows x 64 c, pos added, fp16
#pragma unroll
    for (int p = 0; p < 4; p++) {
        int idx = tid + p * 256;
        int r = idx >> 4;
        int c4 = (idx & 15) * 4;
        int srow = s0 + r;
        int y = srow / 48, x = srow % 48;
        float4 a  = *(const float4*)&src[((size_t)(b * S_TOT + srow)) * 64 + c4];
        float4 py = *(const float4*)&pos_y[y * 64 + c4];
        float4 px = *(const float4*)&pos_x[x * 64 + c4];
        __half2* d = (__half2*)&Xs[r * XWH + c4];
        d[0] = __floats2half2_rn(a.x + py.x + px.x, a.y + py.y + px.y);
        d[1] = __floats2half2_rn(a.z + py.z + px.z, a.w + py.w + px.w);
    }
    // W tile: 64 c-rows x 256 cols, fp16
#pragma unroll
    for (int p = 0; p < 16; p++) {
        int idx = tid + p * 256;
        int c = idx >> 6;
        int j4 = (idx & 63) * 4;
        float4 w = *(const float4*)&W[c * 256 + j4];
        __half2* d = (__half2*)&Ws[c * WSH + j4];
        d[0] = __floats2half2_rn(w.x, w.y);
        d[1] = __floats2half2_rn(w.z, w.w);
    }
    __syncthreads();

    const uint32_t xs_u32 = (uint32_t)__cvta_generic_to_shared(Xs);
    const uint32_t ws_u32 = (uint32_t)__cvta_generic_to_shared(Ws);

    uint32_t qa[4][4];
#pragma unroll
    for (int k = 0; k < 4; k++) {
        uint32_t addr = xs_u32 +
            ((wm0 + (grp & 1) * 8 + l8) * XWH + k * 16 + (grp >> 1) * 8) * 2;
        ldm_x4(qa[k][0], qa[k][1], qa[k][2], qa[k][3], addr);
    }

    float acc[16][4];
#pragma unroll
    for (int n = 0; n < 16; n++)
        acc[n][0] = acc[n][1] = acc[n][2] = acc[n][3] = 0.f;

    const int w_row_off = (grp & 1) * 8 + l8;
    const int w_col_off = (grp >> 1) * 8;
#pragma unroll
    for (int k = 0; k < 4; k++) {
#pragma unroll
        for (int nt = 0; nt < 8; nt++) {
            uint32_t b0, b1, b2, b3;
            uint32_t addr = ws_u32 +
                ((k * 16 + w_row_off) * WSH + jt0 + nt * 16 + w_col_off) * 2;
            ldm_x4_t(b0, b1, b2, b3, addr);
            mma_f16(acc[2*nt][0], acc[2*nt][1], acc[2*nt][2], acc[2*nt][3],
                    qa[k][0], qa[k][1], qa[k][2], qa[k][3], b0, b1);
            mma_f16(acc[2*nt+1][0], acc[2*nt+1][1], acc[2*nt+1][2], acc[2*nt+1][3],
                    qa[k][0], qa[k][1], qa[k][2], qa[k][3], b2, b3);
        }
    }

    const float sc = (proj == 0) ? 0.125f * 1.4426950408889634f : 1.0f;
    __half* dst = g_qkv + (size_t)proj * QKV_STRIDE;
    const size_t row0 = (size_t)(m0 + wm0 + gid) * 256 + jt0;
    const size_t row1 = (size_t)(m0 + wm0 + gid + 8) * 256 + jt0;
#pragma unroll
    for (int n = 0; n < 16; n++) {
        float2 bb = *(const float2*)&bias[jt0 + n * 8 + 2 * tig];
        *(__half2*)&dst[row0 + n * 8 + 2 * tig] =
            __floats2half2_rn((acc[n][0] + bb.x) * sc, (acc[n][1] + bb.y) * sc);
        *(__half2*)&dst[row1 + n * 8 + 2 * tig] =
            __floats2half2_rn((acc[n][2] + bb.x) * sc, (acc[n][3] + bb.y) * sc);
    }
}

// ---------------------------------------------------------------------------
// Kernel B: flash attention, fp16 m16n8k16 mma, 3-stage cp.async pipeline
// (refill after compute; one sync/iter). Round-14 math (exp2f fp32 + FADD l)
// restructured into TWO independent 32-token HALF-TILES per iteration: each
// half runs its own GEMM1 -> exp -> GEMM2 chain, giving the scheduler two
// interleavable chains per warp (fills tensor-pipe bubbles during exp).
// Accumulator chains are order-identical to round 14 -> bit-identical result.
// Dynamic smem: Ks0..2 | Vs0..2, each 64*72 halves -> 55296 B.
// ---------------------------------------------------------------------------
#define KVH 72
#define NUM_KT 36
#define STG_BYTES (64 * KVH * 2)            // 9216
#define ATTN_DYN_BYTES (6 * STG_BYTES)      // 55296

__global__ __launch_bounds__(256, 2) void attn_kernel()
{
    extern __shared__ __align__(16) __half dyn_sm[];

    const int tid  = threadIdx.x;
    const int wid  = tid >> 5;
    const int lane = tid & 31;
    const int gid  = lane >> 2;
    const int tig  = lane & 3;
    const int grp  = lane >> 3;
    const int l8   = lane & 7;
    const int wm0  = wid * 16;

    const int m0 = blockIdx.x * 128;
    const int bh = blockIdx.y;
    const int b = bh >> 2, h = bh & 3;

    const __half* qbase = g_qkv + ((size_t)(b * S_TOT)) * 256 + h * 64;
    const __half* kbase = g_qkv + QKV_STRIDE     + ((size_t)(b * S_TOT)) * 256 + h * 64;
    const __half* vbase = g_qkv + 2 * QKV_STRIDE + ((size_t)(b * S_TOT)) * 256 + h * 64;

    const uint32_t base_u32 = (uint32_t)__cvta_generic_to_shared(dyn_sm);
    const uint32_t ksb[3] = { base_u32, base_u32 + STG_BYTES, base_u32 + 2 * STG_BYTES };
    const uint32_t vsb[3] = { base_u32 + 3 * STG_BYTES, base_u32 + 4 * STG_BYTES,
                              base_u32 + 5 * STG_BYTES };

    auto issue_tile = [&](int kt, int stg) {
#pragma unroll
        for (int p = 0; p < 2; p++) {
            int idx = tid + p * 256;
            int tok = idx >> 3;
            int hc  = (idx & 7) * 8;
            size_t grow = (size_t)(kt * 64 + tok) * 256 + hc;
            cp_async16(ksb[stg] + (tok * KVH + hc) * 2, kbase + grow);
            cp_async16(vsb[stg] + (tok * KVH + hc) * 2, vbase + grow);
        }
    };

    issue_tile(0, 0); cp_commit();
    issue_tile(1, 1); cp_commit();

    // Q fragments direct from gmem (L2-resident)
    uint32_t qa[4][4];
    {
        const __half* qr0 = qbase + (size_t)(m0 + wm0 + gid) * 256;
        const __half* qr1 = qr0 + (size_t)8 * 256;
#pragma unroll
        for (int k = 0; k < 4; k++) {
            qa[k][0] = *(const uint32_t*)&qr0[k * 16 + 2 * tig];
            qa[k][1] = *(const uint32_t*)&qr1[k * 16 + 2 * tig];
            qa[k][2] = *(const uint32_t*)&qr0[k * 16 + 2 * tig + 8];
            qa[k][3] = *(const uint32_t*)&qr1[k * 16 + 2 * tig + 8];
        }
    }

    const int k_tok_off = (grp >> 1) * 8 + l8;
    const int k_col_off = (grp & 1) * 8;
    const int v_tok_off = (grp & 1) * 8 + l8;
    const int v_d_off   = (grp >> 1) * 8;

    float oacc[8][4];
#pragma unroll
    for (int n = 0; n < 8; n++)
        oacc[n][0] = oacc[n][1] = oacc[n][2] = oacc[n][3] = 0.f;
    float l_run0 = 0.f, l_run1 = 0.f;

    int buf = 0;
    for (int kt = 0; kt < NUM_KT; kt++) {
        cp_wait1();          // tile kt complete (tile kt+1 may be in flight)
        __syncthreads();     // tile kt visible; all warps finished iter kt-1

        // ==== two independent 32-token half-tiles ====
#pragma unroll
        for (int half = 0; half < 2; half++) {
            // ---- GEMM1 (half): S = Q * K^T for tokens half*32..+31 ----
            float sacc[4][4];
#pragma unroll
            for (int n = 0; n < 4; n++)
                sacc[n][0] = sacc[n][1] = sacc[n][2] = sacc[n][3] = 0.f;
#pragma unroll
            for (int k = 0; k < 4; k++) {
#pragma unroll
                for (int ntp = 0; ntp < 2; ntp++) {
                    uint32_t b0, b1, b2, b3;
                    uint32_t addr = ksb[buf] +
                        (((half * 2 + ntp) * 16 + k_tok_off) * KVH +
                         k * 16 + k_col_off) * 2;
                    ldm_x4(b0, b1, b2, b3, addr);
                    mma_f16(sacc[2*ntp][0], sacc[2*ntp][1], sacc[2*ntp][2], sacc[2*ntp][3],
                            qa[k][0], qa[k][1], qa[k][2], qa[k][3], b0, b1);
                    mma_f16(sacc[2*ntp+1][0], sacc[2*ntp+1][1], sacc[2*ntp+1][2], sacc[2*ntp+1][3],
                            qa[k][0], qa[k][1], qa[k][2], qa[k][3], b2, b3);
                }
            }

            // ---- Softmax numerator (half): p = exp2(s), fp32 l partials ----
            uint32_t ph[4][2];
#pragma unroll
            for (int n = 0; n < 4; n++) {
                float p0 = exp2f(sacc[n][0]);
                float p1 = exp2f(sacc[n][1]);
                float p2 = exp2f(sacc[n][2]);
                float p3 = exp2f(sacc[n][3]);
                l_run0 += p0 + p1;
                l_run1 += p2 + p3;
                ph[n][0] = h2_as_u32(__floats2half2_rn(p0, p1));
                ph[n][1] = h2_as_u32(__floats2half2_rn(p2, p3));
            }

            // ---- GEMM2 (half): O += P_half * V_half ----
#pragma unroll
            for (int j = 0; j < 2; j++) {
                uint32_t a0 = ph[2*j][0],   a1 = ph[2*j][1];
                uint32_t a2 = ph[2*j+1][0], a3 = ph[2*j+1][1];
#pragma unroll
                for (int ntp = 0; ntp < 4; ntp++) {
                    uint32_t b0, b1, b2, b3;
                    uint32_t addr = vsb[buf] +
                        (((half * 2 + j) * 16 + v_tok_off) * KVH +
                         ntp * 16 + v_d_off) * 2;
                    ldm_x4_t(b0, b1, b2, b3, addr);
                    mma_f16(oacc[2*ntp][0], oacc[2*ntp][1], oacc[2*ntp][2], oacc[2*ntp][3],
                            a0, a1, a2, a3, b0, b1);
                    mma_f16(oacc[2*ntp+1][0], oacc[2*ntp+1][1], oacc[2*ntp+1][2], oacc[2*ntp+1][3],
                            a0, a1, a2, a3, b2, b3);
                }
            }
        }

        // Refill AFTER compute; target (buf+2)%3 = iter kt-1's buffer.
        if (kt + 2 < NUM_KT) {
            int nstg = buf + 2; if (nstg >= 3) nstg -= 3;
            issue_tile(kt + 2, nstg);
        }
        cp_commit();
        buf++; if (buf == 3) buf = 0;
    }

    // ---- Epilogue: quad reduction of l, normalize, store fp16 ----
#pragma unroll
    for (int off = 1; off <= 2; off <<= 1) {
        l_run0 += __shfl_xor_sync(0xffffffffu, l_run0, off);
        l_run1 += __shfl_xor_sync(0xffffffffu, l_run1, off);
    }
    float inv0 = 1.0f / l_run0;
    float inv1 = 1.0f / l_run1;
    __half* c0p = g_ctx + (size_t)(b * S_TOT + m0 + wm0 + gid) * 256 + h * 64;
    __half* c1p = g_ctx + (size_t)(b * S_TOT + m0 + wm0 + gid + 8) * 256 + h * 64;
#pragma unroll
    for (int n = 0; n < 8; n++) {
        *(__half2*)&c0p[n * 8 + 2 * tig] =
            __floats2half2_rn(oacc[n][0] * inv0, oacc[n][1] * inv0);
        *(__half2*)&c1p[n * 8 + 2 * tig] =
            __floats2half2_rn(oacc[n][2] * inv1, oacc[n][3] * inv1);
    }
}

// ---------------------------------------------------------------------------
// Kernel C: output projection on fp16 tensor cores.  (round-14 exact)
// grid 144, 128 thr = 4 warps; Wo staged via 4 chunked cp.async groups
// with progressive waits (compute chunk c overlaps flight of c+1..3).
// ---------------------------------------------------------------------------
__global__ __launch_bounds__(128) void out_proj_kernel(
    const float* __restrict__ bo, float* __restrict__ out)
{
    __shared__ __align__(16) __half Wos[256 * XWH];

    const int tid  = threadIdx.x;
    const int wid  = tid >> 5;
    const int lane = tid & 31;
    const int gid  = lane >> 2;
    const int tig  = lane & 3;
    const int grp  = lane >> 3;
    const int l8   = lane & 7;
    const int wm0  = wid * 16;
    const int m0 = blockIdx.x * 64;

    const uint32_t ws_u32 = (uint32_t)__cvta_generic_to_shared(Wos);

#pragma unroll
    for (int c = 0; c < 4; c++) {
#pragma unroll
        for (int p = 0; p < 4; p++) {
            int idx = tid + p * 128;            // 0..511
            int r  = c * 64 + (idx >> 3);
            int ch = (idx & 7) * 8;
            cp_async16(ws_u32 + (r * XWH + ch) * 2, g_wo16 + r * 64 + ch);
        }
        cp_commit();
    }

    const int w_row_off = (grp & 1) * 8 + l8;
    const int w_col_off = (grp >> 1) * 8;

    const __half* cr0 = g_ctx + (size_t)(m0 + wm0 + gid) * 256;
    const __half* cr1 = cr0 + (size_t)8 * 256;

    float acc[8][4];
#pragma unroll
    for (int n = 0; n < 8; n++)
        acc[n][0] = acc[n][1] = acc[n][2] = acc[n][3] = 0.f;

#define OUT_CHUNK(c)                                                          \
    do {                                                                      \
        CP_WAIT_N(3 - (c));                                                   \
        __syncthreads();                                                      \
        _Pragma("unroll")                                                     \
        for (int kk = 0; kk < 4; kk++) {                                      \
            int k = (c) * 4 + kk;                                             \
            uint32_t a0 = *(const uint32_t*)&cr0[k * 16 + 2 * tig];           \
            uint32_t a1 = *(const uint32_t*)&cr1[k * 16 + 2 * tig];           \
            uint32_t a2 = *(const uint32_t*)&cr0[k * 16 + 2 * tig + 8];       \
            uint32_t a3 = *(const uint32_t*)&cr1[k * 16 + 2 * tig + 8];       \
            _Pragma("unroll")                                                 \
            for (int nt = 0; nt < 4; nt++) {                                  \
                uint32_t b0, b1, b2, b3;                                      \
                uint32_t addr = ws_u32 +                                      \
                    ((k * 16 + w_row_off) * XWH + nt * 16 + w_col_off) * 2;   \
                ldm_x4_t(b0, b1, b2, b3, addr);                               \
                mma_f16(acc[2*nt][0], acc[2*nt][1], acc[2*nt][2], acc[2*nt][3],\
                        a0, a1, a2, a3, b0, b1);                              \
                mma_f16(acc[2*nt+1][0], acc[2*nt+1][1], acc[2*nt+1][2],       \
                        acc[2*nt+1][3], a0, a1, a2, a3, b2, b3);              \
            }                                                                 \
        }                                                                     \
    } while (0)

    OUT_CHUNK(0);
    OUT_CHUNK(1);
    OUT_CHUNK(2);
    OUT_CHUNK(3);
#undef OUT_CHUNK

    const size_t row0 = (size_t)(m0 + wm0 + gid) * 64;
    const size_t row1 = (size_t)(m0 + wm0 + gid + 8) * 64;
#pragma unroll
    for (int n = 0; n < 8; n++) {
        float2 bb = *(const float2*)&bo[n * 8 + 2 * tig];
        *(float2*)&out[row0 + n * 8 + 2 * tig] =
            make_float2(acc[n][0] + bb.x, acc[n][1] + bb.y);
        *(float2*)&out[row1 + n * 8 + 2 * tig] =
            make_float2(acc[n][2] + bb.x, acc[n][3] + bb.y);
    }
}

// ---------------------------------------------------------------------------
extern "C" void kernel_launch(void* const* d_in, const int* in_sizes, int n_in,
                              void* d_out, int out_size)
{
    const float* inp   = (const float*)d_in[0];
    const float* outp  = (const float*)d_in[1];
    const float* pos_y = (const float*)d_in[2];
    const float* pos_x = (const float*)d_in[3];
    const float* Wq    = (const float*)d_in[4];
    const float* bq    = (const float*)d_in[5];
    const float* Wk    = (const float*)d_in[6];
    const float* bk    = (const float*)d_in[7];
    const float* Wv    = (const float*)d_in[8];
    const float* bv    = (const float*)d_in[9];
    const float* Wo    = (const float*)d_in[10];
    const float* bo    = (const float*)d_in[11];

    (void)cudaFuncSetAttribute(attn_kernel,
                               cudaFuncAttributeMaxDynamicSharedMemorySize,
                               ATTN_DYN_BYTES);

    qkv_proj_kernel<<<dim3(144, 4), 256>>>(inp, outp, pos_y, pos_x,
                                           Wq, bq, Wk, bk, Wv, bv, Wo);
    attn_kernel<<<dim3(18, 16), 256, ATTN_DYN_BYTES>>>();
    out_proj_kernel<<<144, 128>>>(bo, (float*)d_out);
}